// round 1
// baseline (speedup 1.0000x reference)
#include <cuda_runtime.h>
#include <math_constants.h>

#define NNODES 8192
#define FIN    512
#define FOUT   256
#define NEG_SLOPE 0.2f

// ---------------- device scratch (no allocations allowed) ----------------
__device__ float g_H[NNODES * FOUT];     // H = X @ W^T   (8 MB)
__device__ float g_s[NNODES];            // H @ a_l
__device__ float g_t[NNODES];            // H @ a_r
__device__ float g_rmax[NNODES];         // per-row max of logits (over adj)
__device__ float g_rsum[NNODES];         // per-row sum exp(logit - rmax)
__device__ int   g_nonb[NNODES];         // 1 if row has no neighbors

// ---------------- Kernel 1: H = X @ W^T (fp32 tiled SGEMM) ----------------
// grid (128, 4), block 256. 64x64 tile per block, BK=32, 4x4 per thread.
__global__ void gemm_H_kernel(const float* __restrict__ X,
                              const float* __restrict__ W) {
    __shared__ float Xs[64][33];
    __shared__ float Ws[64][33];
    const int tid = threadIdx.x;
    const int tx = tid & 15;        // 0..15 -> 4 cols each
    const int ty = tid >> 4;        // 0..15 -> 4 rows each
    const int row0 = blockIdx.x * 64;
    const int col0 = blockIdx.y * 64;

    float acc[4][4];
#pragma unroll
    for (int r = 0; r < 4; r++)
#pragma unroll
        for (int c = 0; c < 4; c++) acc[r][c] = 0.f;

    for (int k0 = 0; k0 < FIN; k0 += 32) {
#pragma unroll
        for (int q = 0; q < 8; q++) {
            int id = tid + q * 256;          // 0..2047
            int r = id >> 5, c = id & 31;
            Xs[r][c] = X[(size_t)(row0 + r) * FIN + k0 + c];
            Ws[r][c] = W[(size_t)(col0 + r) * FIN + k0 + c];
        }
        __syncthreads();
#pragma unroll
        for (int kk = 0; kk < 32; kk++) {
            float a[4], b[4];
#pragma unroll
            for (int r = 0; r < 4; r++) a[r] = Xs[ty * 4 + r][kk];
#pragma unroll
            for (int c = 0; c < 4; c++) b[c] = Ws[tx * 4 + c][kk];
#pragma unroll
            for (int r = 0; r < 4; r++)
#pragma unroll
                for (int c = 0; c < 4; c++) acc[r][c] += a[r] * b[c];
        }
        __syncthreads();
    }
#pragma unroll
    for (int r = 0; r < 4; r++)
#pragma unroll
        for (int c = 0; c < 4; c++)
            g_H[(size_t)(row0 + ty * 4 + r) * FOUT + col0 + tx * 4 + c] = acc[r][c];
}

// ---------------- Kernel 2: s = H a_l, t = H a_r ----------------
// block 256 = 8 warps, one row per warp. grid 1024.
__global__ void st_kernel(const float* __restrict__ attn_w) {
    const int lane = threadIdx.x & 31;
    const int warp = threadIdx.x >> 5;
    const int row = blockIdx.x * 8 + warp;
    float s = 0.f, t = 0.f;
#pragma unroll
    for (int o = lane; o < FOUT; o += 32) {
        float h = g_H[(size_t)row * FOUT + o];
        s += h * attn_w[o];
        t += h * attn_w[FOUT + o];
    }
#pragma unroll
    for (int off = 16; off; off >>= 1) {
        s += __shfl_down_sync(0xffffffffu, s, off);
        t += __shfl_down_sync(0xffffffffu, t, off);
    }
    if (lane == 0) { g_s[row] = s; g_t[row] = t; }
}

// ---------------- Kernel 3: per-row online softmax stats over M ----------------
// one block (256 threads) per row.
__global__ void stats_kernel(const float* __restrict__ M) {
    const int i = blockIdx.x;
    const int tid = threadIdx.x;
    const float si = g_s[i];

    float mx = -CUDART_INF_F;
    float sm = 0.f;
    int cnt = 0;
    const float* Mi = M + (size_t)i * NNODES;
    for (int j = tid; j < NNODES; j += 256) {
        float m = Mi[j];
        if (m > 0.f) {
            float v = si + g_t[j];
            float e = (v >= 0.f) ? v : NEG_SLOPE * v;
            float lg = m * e;
            cnt++;
            if (lg > mx) { sm = sm * __expf(mx - lg) + 1.f; mx = lg; }
            else         { sm += __expf(lg - mx); }
        }
    }

    __shared__ float rm[256];
    __shared__ float rs[256];
    __shared__ int   rc[256];
    rm[tid] = mx; rs[tid] = sm; rc[tid] = cnt;
    __syncthreads();
    for (int off = 128; off; off >>= 1) {
        if (tid < off) {
            float m1 = rm[tid], s1 = rs[tid];
            float m2 = rm[tid + off], s2 = rs[tid + off];
            if (m2 > m1) { float tm = m1; m1 = m2; m2 = tm; float ts = s1; s1 = s2; s2 = ts; }
            if (s2 > 0.f) s1 += s2 * __expf(m2 - m1);   // m1 finite here
            rm[tid] = m1; rs[tid] = s1; rc[tid] += rc[tid + off];
        }
        __syncthreads();
    }
    if (tid == 0) {
        g_rmax[i] = rm[0];
        g_rsum[i] = rs[0];
        g_nonb[i] = (rc[0] == 0) ? 1 : 0;
    }
}

// ---------------- Kernel 4: Z = sigmoid( (P @ H) / rowsum ) ----------------
// BM=32 rows per block over all 256 cols, K-loop over 8192 in BK=32 chunks.
// block 256: cx = tid&31 -> 8 cols each; ry = tid>>5 (0..7) -> 4 rows each.
#define BM 32
#define BK 32
__global__ void attn_kernel(const float* __restrict__ M,
                            float* __restrict__ out) {
    __shared__ float Ps[BM][BK + 1];     // P[row][k]
    __shared__ float Hs[BK][FOUT];       // H[k][col]  (32 KB)
    __shared__ float s_sh[BM];
    __shared__ float rmax_sh[BM];

    const int tid = threadIdx.x;
    const int cx = tid & 31;             // col group
    const int ry = tid >> 5;             // row group
    const int row0 = blockIdx.x * BM;

    if (tid < BM) {
        s_sh[tid] = g_s[row0 + tid];
        rmax_sh[tid] = g_rmax[row0 + tid];
    }
    __syncthreads();

    float acc[4][8];
#pragma unroll
    for (int r = 0; r < 4; r++)
#pragma unroll
        for (int c = 0; c < 8; c++) acc[r][c] = 0.f;

    for (int k0 = 0; k0 < NNODES; k0 += BK) {
        // P tile: 32x32, each thread 4 elements (coalesced over M rows)
#pragma unroll
        for (int q = 0; q < 4; q++) {
            int id = tid + q * 256;      // 0..1023
            int r = id >> 5, k = id & 31;
            float m = M[(size_t)(row0 + r) * NNODES + k0 + k];
            float p = 0.f;
            if (m > 0.f) {
                float v = s_sh[r] + g_t[k0 + k];
                float e = (v >= 0.f) ? v : NEG_SLOPE * v;
                p = __expf(m * e - rmax_sh[r]);
            }
            Ps[r][k] = p;
        }
        // H tile: 32x256 via float4, each thread 8 vectors
#pragma unroll
        for (int q = 0; q < 8; q++) {
            int id4 = tid + q * 256;     // 0..2047 float4s
            int kk = id4 >> 6;           // /64
            int col = (id4 & 63) << 2;
            *reinterpret_cast<float4*>(&Hs[kk][col]) =
                *reinterpret_cast<const float4*>(&g_H[(size_t)(k0 + kk) * FOUT + col]);
        }
        __syncthreads();

#pragma unroll
        for (int kk = 0; kk < BK; kk++) {
            float b[8];
            float4 b0 = *reinterpret_cast<const float4*>(&Hs[kk][cx * 8]);
            float4 b1 = *reinterpret_cast<const float4*>(&Hs[kk][cx * 8 + 4]);
            b[0] = b0.x; b[1] = b0.y; b[2] = b0.z; b[3] = b0.w;
            b[4] = b1.x; b[5] = b1.y; b[6] = b1.z; b[7] = b1.w;
            float a[4];
#pragma unroll
            for (int r = 0; r < 4; r++) a[r] = Ps[ry * 4 + r][kk];
#pragma unroll
            for (int r = 0; r < 4; r++)
#pragma unroll
                for (int c = 0; c < 8; c++) acc[r][c] += a[r] * b[c];
        }
        __syncthreads();
    }

    // epilogue: normalize, no-neighbor override, sigmoid
#pragma unroll
    for (int r = 0; r < 4; r++) {
        int row = row0 + ry * 4 + r;
        float inv = 1.f / g_rsum[row];
        int nb = g_nonb[row];
#pragma unroll
        for (int c = 0; c < 8; c++) {
            int col = cx * 8 + c;
            float u = acc[r][c] * inv;
            if (nb) u = g_H[(size_t)row * FOUT + col];   // alpha = one-hot(self)
            out[(size_t)row * FOUT + col] = 1.f / (1.f + __expf(-u));
        }
    }
}

// ---------------- launch ----------------
extern "C" void kernel_launch(void* const* d_in, const int* in_sizes, int n_in,
                              void* d_out, int out_size) {
    const float *X = nullptr, *M = nullptr, *W = nullptr, *AW = nullptr;
    for (int i = 0; i < n_in; i++) {
        switch (in_sizes[i]) {
            case NNODES * FIN:    X  = (const float*)d_in[i]; break;  // 4194304
            case NNODES * NNODES: M  = (const float*)d_in[i]; break;  // 67108864 (needs int; fits)
            case FOUT * FIN:      W  = (const float*)d_in[i]; break;  // 131072
            case 2 * FOUT:        AW = (const float*)d_in[i]; break;  // 512
            default: break;
        }
    }
    float* out = (float*)d_out;

    dim3 gH(NNODES / 64, FOUT / 64);
    gemm_H_kernel<<<gH, 256>>>(X, W);
    st_kernel<<<NNODES / 8, 256>>>(AW);
    stats_kernel<<<NNODES, 256>>>(M);
    attn_kernel<<<NNODES / BM, 256>>>(M, out);
}

// round 3
// speedup vs baseline: 3.7259x; 3.7259x over previous
#include <cuda_runtime.h>
#include <cuda_bf16.h>
#include <math_constants.h>
#include <cstdint>

#define NNODES 8192
#define FIN    512
#define FOUT   256
#define NEG_SLOPE 0.2f

#define BM 64
#define BK 64
#define NCHUNK (NNODES / BK)     // 128
#define ATTN_THREADS 256

// ---------------- device scratch ----------------
__device__ float         g_H [NNODES * FOUT];   // H fp32 row-major
__device__ __nv_bfloat16 g_HT[FOUT * NNODES];   // H^T bf16 (n-major rows, k contiguous)
__device__ float         g_s [NNODES];
__device__ float         g_t [NNODES];

// ---------------- helpers (all base PTX, sm_80-compatible) ----------------
static __device__ __forceinline__ uint32_t smem_u32(const void* p) {
    uint32_t a;
    asm("{ .reg .u64 t; cvta.to.shared.u64 t, %1; cvt.u32.u64 %0, t; }" : "=r"(a) : "l"(p));
    return a;
}
static __device__ __forceinline__ void cp_async16(uint32_t dst, const void* src) {
    asm volatile("cp.async.cg.shared.global [%0], [%1], 16;" :: "r"(dst), "l"(src));
}
static __device__ __forceinline__ void cp_commit() {
    asm volatile("cp.async.commit_group;" ::: "memory");
}
static __device__ __forceinline__ void cp_wait_all() {
    asm volatile("cp.async.wait_group 0;" ::: "memory");
}
static __device__ __forceinline__ void ldm_x4(uint32_t& r0, uint32_t& r1,
                                              uint32_t& r2, uint32_t& r3, uint32_t addr) {
    asm volatile("ldmatrix.sync.aligned.m8n8.x4.shared.b16 {%0, %1, %2, %3}, [%4];"
                 : "=r"(r0), "=r"(r1), "=r"(r2), "=r"(r3) : "r"(addr));
}
static __device__ __forceinline__ void mma_16816(float* d, const uint32_t* a, const uint32_t* b) {
    asm volatile(
        "mma.sync.aligned.m16n8k16.row.col.f32.bf16.bf16.f32 "
        "{%0, %1, %2, %3}, {%4, %5, %6, %7}, {%8, %9}, {%0, %1, %2, %3};"
        : "+f"(d[0]), "+f"(d[1]), "+f"(d[2]), "+f"(d[3])
        : "r"(a[0]), "r"(a[1]), "r"(a[2]), "r"(a[3]), "r"(b[0]), "r"(b[1]));
}
static __device__ __forceinline__ uint32_t sw128(uint32_t b) { return b ^ ((b >> 3) & 0x70); }

// ---------------- Kernel 1: H = X @ W^T (fp32), also writes HT bf16 ----------------
__global__ void gemm_H_kernel(const float* __restrict__ X,
                              const float* __restrict__ W) {
    __shared__ float Xs[64][33];
    __shared__ float Ws[64][33];
    const int tid = threadIdx.x;
    const int tx = tid & 15;
    const int ty = tid >> 4;
    const int row0 = blockIdx.x * 64;
    const int col0 = blockIdx.y * 64;

    float acc[4][4];
#pragma unroll
    for (int r = 0; r < 4; r++)
#pragma unroll
        for (int c = 0; c < 4; c++) acc[r][c] = 0.f;

    for (int k0 = 0; k0 < FIN; k0 += 32) {
#pragma unroll
        for (int q = 0; q < 8; q++) {
            int id = tid + q * 256;
            int r = id >> 5, c = id & 31;
            Xs[r][c] = X[(size_t)(row0 + r) * FIN + k0 + c];
            Ws[r][c] = W[(size_t)(col0 + r) * FIN + k0 + c];
        }
        __syncthreads();
#pragma unroll
        for (int kk = 0; kk < 32; kk++) {
            float a[4], b[4];
#pragma unroll
            for (int r = 0; r < 4; r++) a[r] = Xs[ty * 4 + r][kk];
#pragma unroll
            for (int c = 0; c < 4; c++) b[c] = Ws[tx * 4 + c][kk];
#pragma unroll
            for (int r = 0; r < 4; r++)
#pragma unroll
                for (int c = 0; c < 4; c++) acc[r][c] += a[r] * b[c];
        }
        __syncthreads();
    }
#pragma unroll
    for (int r = 0; r < 4; r++)
#pragma unroll
        for (int c = 0; c < 4; c++) {
            int row = row0 + ty * 4 + r;
            int col = col0 + tx * 4 + c;
            float v = acc[r][c];
            g_H[(size_t)row * FOUT + col] = v;
            g_HT[(size_t)col * NNODES + row] = __float2bfloat16(v);
        }
}

// ---------------- Kernel 2: s = H a_l, t = H a_r ----------------
__global__ void st_kernel(const float* __restrict__ attn_w) {
    const int lane = threadIdx.x & 31;
    const int warp = threadIdx.x >> 5;
    const int row = blockIdx.x * 8 + warp;
    float s = 0.f, t = 0.f;
#pragma unroll
    for (int o = lane; o < FOUT; o += 32) {
        float h = g_H[(size_t)row * FOUT + o];
        s += h * attn_w[o];
        t += h * attn_w[FOUT + o];
    }
#pragma unroll
    for (int off = 16; off; off >>= 1) {
        s += __shfl_down_sync(0xffffffffu, s, off);
        t += __shfl_down_sync(0xffffffffu, t, off);
    }
    if (lane == 0) { g_s[row] = s; g_t[row] = t; }
}

// ---------------- Kernel 3: flash-style mma.sync attention ----------------
// SMEM (offsets from 1024-aligned base):
#define PS_OFF0 0u          // P tile buf0: 64 rows x 128B (SW128)  = 8 KB
#define PS_OFF1 8192u
#define HS_OFF0 16384u      // HT tile buf0: 256 rows x 128B (SW128) = 32 KB
#define HS_OFF1 49152u
#define RS_OFF  81920u      // 64 floats rowsum
#define TS_OFF  82176u      // t_sh: 2 x 64 floats
#define SMEM_DYN 83712      // 82688 + 1024 align slack

__global__ void __launch_bounds__(ATTN_THREADS)
attn_mma_kernel(const float* __restrict__ M, float* __restrict__ out) {
    extern __shared__ char dsm[];
    const uint32_t raw = smem_u32(dsm);
    const uint32_t base = (raw + 1023u) & ~1023u;
    char* al = dsm + (base - raw);

    const int tid  = threadIdx.x;
    const int lane = tid & 31;
    const int wid  = tid >> 5;
    const int row0 = blockIdx.x * BM;

    float* rowsum = (float*)(al + RS_OFF);
    float* t_sh   = (float*)(al + TS_OFF);   // [2][64]

    // per-thread P-producer assignment: row r = tid/4, 16 cols starting at (tid%4)*16
    const int pr_r   = tid >> 2;
    const int pr_seg = tid & 3;
    const float si = g_s[row0 + pr_r];
    const float* Mrow = M + (size_t)(row0 + pr_r) * NNODES + pr_seg * 16;

    // warp MMA tile
    const int mrow0 = (wid & 1) * 32;
    const int ncol0 = (wid >> 1) * 64;

    float acc[2][8][4];
#pragma unroll
    for (int mt = 0; mt < 2; mt++)
#pragma unroll
        for (int nt = 0; nt < 8; nt++)
#pragma unroll
            for (int e = 0; e < 4; e++) acc[mt][nt][e] = 0.f;

    // ---- prologue: prefetch chunk 0 ----
#pragma unroll
    for (int q = 0; q < 8; q++) {
        int id = tid + q * ATTN_THREADS;        // 0..2047
        int n = id >> 3, kq = id & 7;
        cp_async16(base + HS_OFF0 + sw128((uint32_t)n * 128u + (uint32_t)kq * 16u),
                   g_HT + (size_t)n * NNODES + kq * 8);
    }
    cp_commit();
    if (tid < BK) t_sh[tid] = g_t[tid];
    float4 mcur[4];
#pragma unroll
    for (int j = 0; j < 4; j++)
        mcur[j] = *reinterpret_cast<const float4*>(Mrow + j * 4);
    float rs_reg = 0.f;

#pragma unroll 2
    for (int c = 0; c < NCHUNK; ++c) {
        const int buf = c & 1;
        const uint32_t ps_off = buf ? PS_OFF1 : PS_OFF0;
        const uint32_t hs_off = buf ? HS_OFF1 : HS_OFF0;
        const uint32_t hs_nxt = buf ? HS_OFF0 : HS_OFF1;

        // step 1: current Hs tile landed; all warps done with the other buffers
        cp_wait_all();
        __syncthreads();

        const int cn = c + 1;
        const bool have_next = (cn < NCHUNK);

        // step 2a: prefetch next Hs tile
        if (have_next) {
#pragma unroll
            for (int q = 0; q < 8; q++) {
                int id = tid + q * ATTN_THREADS;
                int n = id >> 3, kq = id & 7;
                cp_async16(base + hs_nxt + sw128((uint32_t)n * 128u + (uint32_t)kq * 16u),
                           g_HT + (size_t)n * NNODES + cn * BK + kq * 8);
            }
        }
        cp_commit();
        if (have_next && tid < BK) t_sh[(buf ^ 1) * BK + tid] = g_t[cn * BK + tid];

        // step 2b: prefetch next M block into registers
        float4 mnext[4];
        if (have_next) {
#pragma unroll
            for (int j = 0; j < 4; j++)
                mnext[j] = *reinterpret_cast<const float4*>(Mrow + cn * BK + j * 4);
        }

        // step 2c: P tile from mcur -> bf16 SW128 SMEM + rowsum
#pragma unroll
        for (int j = 0; j < 4; j++) {
            float pr[4];
#pragma unroll
            for (int e = 0; e < 4; e++) {
                float m = (&mcur[j].x)[e];
                int k = pr_seg * 16 + j * 4 + e;
                float v = si + t_sh[buf * BK + k];
                float lr = (v >= 0.f) ? v : NEG_SLOPE * v;
                float pv = (m > 0.f) ? __expf(m * lr) : 0.f;
                pr[e] = __bfloat162float(__float2bfloat16(pv));  // match MMA numerator
            }
            uint2 packed;
            __nv_bfloat162 p01 = __floats2bfloat162_rn(pr[0], pr[1]);
            __nv_bfloat162 p23 = __floats2bfloat162_rn(pr[2], pr[3]);
            packed.x = *reinterpret_cast<uint32_t*>(&p01);
            packed.y = *reinterpret_cast<uint32_t*>(&p23);
            uint32_t byte = (uint32_t)pr_r * 128u + (uint32_t)(pr_seg * 16 + j * 4) * 2u;
            *reinterpret_cast<uint2*>(al + ps_off + sw128(byte)) = packed;
            rs_reg += pr[0] + pr[1] + pr[2] + pr[3];
        }

        // step 3: P visible to all warps
        __syncthreads();

        // step 4: 4 k16 steps of mma over this chunk
#pragma unroll
        for (int ks = 0; ks < 4; ks++) {
            const uint32_t kb = (uint32_t)(ks * 16 + (lane >> 4) * 8) * 2u;  // byte offset in row
            uint32_t a[2][4];
#pragma unroll
            for (int mt = 0; mt < 2; mt++) {
                uint32_t addr = base + ps_off +
                    sw128((uint32_t)(mrow0 + mt * 16 + (lane & 15)) * 128u + kb);
                ldm_x4(a[mt][0], a[mt][1], a[mt][2], a[mt][3], addr);
            }
            uint32_t b[8][2];
#pragma unroll
            for (int np = 0; np < 4; np++) {
                uint32_t r0, r1, r2, r3;
                uint32_t addr = base + hs_off +
                    sw128((uint32_t)(ncol0 + np * 16 + (lane & 15)) * 128u + kb);
                ldm_x4(r0, r1, r2, r3, addr);
                b[2 * np][0] = r0; b[2 * np][1] = r2;
                b[2 * np + 1][0] = r1; b[2 * np + 1][1] = r3;
            }
#pragma unroll
            for (int mt = 0; mt < 2; mt++)
#pragma unroll
                for (int nt = 0; nt < 8; nt++)
                    mma_16816(acc[mt][nt], a[mt], b[nt]);
        }

        // rotate M registers
#pragma unroll
        for (int j = 0; j < 4; j++) mcur[j] = mnext[j];
    }

    // ---- rowsum: reduce the 4 threads sharing a row ----
    rs_reg += __shfl_xor_sync(0xffffffffu, rs_reg, 1);
    rs_reg += __shfl_xor_sync(0xffffffffu, rs_reg, 2);
    if ((tid & 3) == 0) rowsum[pr_r] = rs_reg;
    __syncthreads();

    // ---- epilogue: normalize, no-neighbor override, sigmoid ----
#pragma unroll
    for (int mt = 0; mt < 2; mt++) {
#pragma unroll
        for (int half = 0; half < 2; half++) {
            const int rl = mrow0 + mt * 16 + (lane >> 2) + half * 8;
            const int row = row0 + rl;
            const float rs = rowsum[rl];
            const bool nb = !(rs > 0.f);
            const float inv = nb ? 0.f : 1.f / rs;
#pragma unroll
            for (int nt = 0; nt < 8; nt++) {
                const int col = ncol0 + nt * 8 + (lane & 3) * 2;
                float u0 = acc[mt][nt][2 * half]     * inv;
                float u1 = acc[mt][nt][2 * half + 1] * inv;
                if (nb) {
                    u0 = g_H[(size_t)row * FOUT + col];
                    u1 = g_H[(size_t)row * FOUT + col + 1];
                }
                float2 z;
                z.x = 1.f / (1.f + __expf(-u0));
                z.y = 1.f / (1.f + __expf(-u1));
                *reinterpret_cast<float2*>(out + (size_t)row * FOUT + col) = z;
            }
        }
    }
}

// ---------------- launch ----------------
extern "C" void kernel_launch(void* const* d_in, const int* in_sizes, int n_in,
                              void* d_out, int out_size) {
    const float *X = nullptr, *M = nullptr, *W = nullptr, *AW = nullptr;
    for (int i = 0; i < n_in; i++) {
        switch (in_sizes[i]) {
            case NNODES * FIN:    X  = (const float*)d_in[i]; break;
            case NNODES * NNODES: M  = (const float*)d_in[i]; break;
            case FOUT * FIN:      W  = (const float*)d_in[i]; break;
            case 2 * FOUT:        AW = (const float*)d_in[i]; break;
            default: break;
        }
    }
    float* out = (float*)d_out;

    cudaFuncSetAttribute(attn_mma_kernel,
                         cudaFuncAttributeMaxDynamicSharedMemorySize, SMEM_DYN);

    dim3 gH(NNODES / 64, FOUT / 64);
    gemm_H_kernel<<<gH, 256>>>(X, W);
    st_kernel<<<NNODES / 8, 256>>>(AW);
    attn_mma_kernel<<<NNODES / BM, ATTN_THREADS, SMEM_DYN>>>(M, out);
}

// round 4
// speedup vs baseline: 5.2000x; 1.3957x over previous
#include <cuda_runtime.h>
#include <cuda_bf16.h>
#include <math_constants.h>
#include <cstdint>

#define NNODES 8192
#define FIN    512
#define FOUT   256
#define NEG_SLOPE 0.2f

#define BM 64
#define BK 64
#define NCHUNK (NNODES / BK)     // 128
#define ATTN_THREADS 256

// ---------------- device scratch ----------------
__device__ float         g_H [NNODES * FOUT];   // H fp32 row-major
__device__ __nv_bfloat16 g_HT[FOUT * NNODES];   // H^T bf16 (n-major rows, k contiguous)
__device__ float         g_s [NNODES];
__device__ float         g_t [NNODES];

// ---------------- helpers (base PTX, sm_80-compatible) ----------------
static __device__ __forceinline__ uint32_t smem_u32(const void* p) {
    uint32_t a;
    asm("{ .reg .u64 t; cvta.to.shared.u64 t, %1; cvt.u32.u64 %0, t; }" : "=r"(a) : "l"(p));
    return a;
}
static __device__ __forceinline__ void cp_async16(uint32_t dst, const void* src) {
    asm volatile("cp.async.cg.shared.global [%0], [%1], 16;" :: "r"(dst), "l"(src));
}
static __device__ __forceinline__ void cp_commit() {
    asm volatile("cp.async.commit_group;" ::: "memory");
}
static __device__ __forceinline__ void cp_wait_all() {
    asm volatile("cp.async.wait_group 0;" ::: "memory");
}
static __device__ __forceinline__ void ldm_x4(uint32_t& r0, uint32_t& r1,
                                              uint32_t& r2, uint32_t& r3, uint32_t addr) {
    asm volatile("ldmatrix.sync.aligned.m8n8.x4.shared.b16 {%0, %1, %2, %3}, [%4];"
                 : "=r"(r0), "=r"(r1), "=r"(r2), "=r"(r3) : "r"(addr));
}
static __device__ __forceinline__ void mma_16816(float* d, const uint32_t* a, const uint32_t* b) {
    asm volatile(
        "mma.sync.aligned.m16n8k16.row.col.f32.bf16.bf16.f32 "
        "{%0, %1, %2, %3}, {%4, %5, %6, %7}, {%8, %9}, {%0, %1, %2, %3};"
        : "+f"(d[0]), "+f"(d[1]), "+f"(d[2]), "+f"(d[3])
        : "r"(a[0]), "r"(a[1]), "r"(a[2]), "r"(a[3]), "r"(b[0]), "r"(b[1]));
}
static __device__ __forceinline__ void mma_tf32(float* d, const uint32_t* a, const uint32_t* b) {
    asm volatile(
        "mma.sync.aligned.m16n8k8.row.col.f32.tf32.tf32.f32 "
        "{%0, %1, %2, %3}, {%4, %5, %6, %7}, {%8, %9}, {%0, %1, %2, %3};"
        : "+f"(d[0]), "+f"(d[1]), "+f"(d[2]), "+f"(d[3])
        : "r"(a[0]), "r"(a[1]), "r"(a[2]), "r"(a[3]), "r"(b[0]), "r"(b[1]));
}
static __device__ __forceinline__ uint32_t f2tf32(float v) {
    uint32_t r;
    asm("cvt.rna.tf32.f32 %0, %1;" : "=r"(r) : "f"(v));
    return r;
}
static __device__ __forceinline__ uint32_t sw128(uint32_t b) { return b ^ ((b >> 3) & 0x70); }

// ---------------- Kernel 1: H = X @ W^T via tf32 mma, writes H fp32 + HT bf16 ----------------
// CTA tile 128x64, BK2=32, 256 threads (8 warps: wm=wid&3 -> 32 rows, wn=wid>>2 -> 32 cols)
#define GPITCH 36      // floats per smem row (conflict-free for 4m+k bank map)
#define XS_OFF0 0u
#define XS_OFF1 18432u                 // 128*36*4
#define WS_OFF0 36864u
#define WS_OFF1 46080u                 // + 64*36*4
#define GEMM_SMEM 55296

__global__ void __launch_bounds__(256)
gemm_H_tf32_kernel(const float* __restrict__ X, const float* __restrict__ W) {
    extern __shared__ char gsm[];
    const uint32_t base = smem_u32(gsm);     // dynamic smem is 16B aligned; pitch multiple of 16B
    float* sm = (float*)gsm;

    const int tid = threadIdx.x;
    const int lane = tid & 31;
    const int wid = tid >> 5;
    const int wm = (wid & 3) * 32;
    const int wn = (wid >> 2) * 32;
    const int row0 = blockIdx.x * 128;
    const int col0 = blockIdx.y * 64;

    float acc[2][4][4];
#pragma unroll
    for (int mt = 0; mt < 2; mt++)
#pragma unroll
        for (int nt = 0; nt < 4; nt++)
#pragma unroll
            for (int e = 0; e < 4; e++) acc[mt][nt][e] = 0.f;

    // prologue: load k-block 0 into buf0
#pragma unroll
    for (int q = 0; q < 4; q++) {
        int id = tid + q * 256;               // X: 1024 float4
        int r = id >> 3, kq = id & 7;
        cp_async16(base + XS_OFF0 + (uint32_t)(r * GPITCH + kq * 4) * 4u,
                   X + (size_t)(row0 + r) * FIN + kq * 4);
    }
#pragma unroll
    for (int q = 0; q < 2; q++) {
        int id = tid + q * 256;               // W: 512 float4
        int r = id >> 3, kq = id & 7;
        cp_async16(base + WS_OFF0 + (uint32_t)(r * GPITCH + kq * 4) * 4u,
                   W + (size_t)(col0 + r) * FIN + kq * 4);
    }
    cp_commit();

    const int a_r = lane >> 2;       // 0..7
    const int a_k = lane & 3;        // 0..3

#pragma unroll 1
    for (int kb = 0; kb < FIN / 32; kb++) {
        const int buf = kb & 1;
        const uint32_t xs = buf ? XS_OFF1 : XS_OFF0;
        const uint32_t ws = buf ? WS_OFF1 : WS_OFF0;
        cp_wait_all();
        __syncthreads();

        if (kb + 1 < FIN / 32) {
            const uint32_t xsn = buf ? XS_OFF0 : XS_OFF1;
            const uint32_t wsn = buf ? WS_OFF0 : WS_OFF1;
            const int k0n = (kb + 1) * 32;
#pragma unroll
            for (int q = 0; q < 4; q++) {
                int id = tid + q * 256;
                int r = id >> 3, kq = id & 7;
                cp_async16(base + xsn + (uint32_t)(r * GPITCH + kq * 4) * 4u,
                           X + (size_t)(row0 + r) * FIN + k0n + kq * 4);
            }
#pragma unroll
            for (int q = 0; q < 2; q++) {
                int id = tid + q * 256;
                int r = id >> 3, kq = id & 7;
                cp_async16(base + wsn + (uint32_t)(r * GPITCH + kq * 4) * 4u,
                           W + (size_t)(col0 + r) * FIN + k0n + kq * 4);
            }
            cp_commit();
        }

        const float* Xs = (const float*)((const char*)sm + xs);
        const float* Ws = (const float*)((const char*)sm + ws);
#pragma unroll
        for (int kk = 0; kk < 32; kk += 8) {
            uint32_t a[2][4];
#pragma unroll
            for (int mt = 0; mt < 2; mt++) {
                const int m = wm + mt * 16 + a_r;
                a[mt][0] = f2tf32(Xs[m * GPITCH + kk + a_k]);
                a[mt][1] = f2tf32(Xs[(m + 8) * GPITCH + kk + a_k]);
                a[mt][2] = f2tf32(Xs[m * GPITCH + kk + a_k + 4]);
                a[mt][3] = f2tf32(Xs[(m + 8) * GPITCH + kk + a_k + 4]);
            }
            uint32_t b[4][2];
#pragma unroll
            for (int nt = 0; nt < 4; nt++) {
                const int n = wn + nt * 8 + a_r;
                b[nt][0] = f2tf32(Ws[n * GPITCH + kk + a_k]);
                b[nt][1] = f2tf32(Ws[n * GPITCH + kk + a_k + 4]);
            }
#pragma unroll
            for (int mt = 0; mt < 2; mt++)
#pragma unroll
                for (int nt = 0; nt < 4; nt++)
                    mma_tf32(acc[mt][nt], a[mt], b[nt]);
        }
    }

    // epilogue: write H fp32 and HT bf16
#pragma unroll
    for (int mt = 0; mt < 2; mt++) {
#pragma unroll
        for (int nt = 0; nt < 4; nt++) {
#pragma unroll
            for (int half = 0; half < 2; half++) {
                const int row = row0 + wm + mt * 16 + (lane >> 2) + half * 8;
                const int col = col0 + wn + nt * 8 + (lane & 3) * 2;
                float v0 = acc[mt][nt][2 * half];
                float v1 = acc[mt][nt][2 * half + 1];
                *reinterpret_cast<float2*>(g_H + (size_t)row * FOUT + col) = make_float2(v0, v1);
                g_HT[(size_t)col * NNODES + row]       = __float2bfloat16(v0);
                g_HT[(size_t)(col + 1) * NNODES + row] = __float2bfloat16(v1);
            }
        }
    }
}

// ---------------- Kernel 2: s = H a_l, t = H a_r ----------------
__global__ void st_kernel(const float* __restrict__ attn_w) {
    const int lane = threadIdx.x & 31;
    const int warp = threadIdx.x >> 5;
    const int row = blockIdx.x * 8 + warp;
    float s = 0.f, t = 0.f;
#pragma unroll
    for (int o = lane; o < FOUT; o += 32) {
        float h = g_H[(size_t)row * FOUT + o];
        s += h * attn_w[o];
        t += h * attn_w[FOUT + o];
    }
#pragma unroll
    for (int off = 16; off; off >>= 1) {
        s += __shfl_down_sync(0xffffffffu, s, off);
        t += __shfl_down_sync(0xffffffffu, t, off);
    }
    if (lane == 0) { g_s[row] = s; g_t[row] = t; }
}

// ---------------- Kernel 3: pipelined flash-style mma.sync attention ----------------
#define PS_OFF0 0u
#define PS_OFF1 8192u
#define HS_OFF0 16384u
#define HS_OFF1 49152u
#define RS_OFF  81920u
#define SMEM_DYN 83456      // 82176 + 1024 align slack

__global__ void __launch_bounds__(ATTN_THREADS)
attn_mma_kernel(const float* __restrict__ M, float* __restrict__ out) {
    extern __shared__ char dsm[];
    const uint32_t raw = smem_u32(dsm);
    const uint32_t base = (raw + 1023u) & ~1023u;
    char* al = dsm + (base - raw);

    const int tid  = threadIdx.x;
    const int lane = tid & 31;
    const int wid  = tid >> 5;
    const int row0 = blockIdx.x * BM;

    float* rowsum = (float*)(al + RS_OFF);

    // P-producer: row = tid/4, 16 cols at (tid%4)*16
    const int pr_r   = tid >> 2;
    const int pr_seg = tid & 3;
    const float si = g_s[row0 + pr_r];
    const float* Mrow = M + (size_t)(row0 + pr_r) * NNODES + pr_seg * 16;
    const float* Trow = g_t + pr_seg * 16;

    // warp MMA tile
    const int mrow0 = (wid & 1) * 32;
    const int ncol0 = (wid >> 1) * 64;

    float acc[2][8][4];
#pragma unroll
    for (int mt = 0; mt < 2; mt++)
#pragma unroll
        for (int nt = 0; nt < 8; nt++)
#pragma unroll
            for (int e = 0; e < 4; e++) acc[mt][nt][e] = 0.f;

    float rs_reg = 0.f;

    // helper lambda-ish macro: compute P(chunk) from 4 float4 M regs into ps buffer
    // (expanded inline below)

    // ---- prologue ----
    // Hs(0) prefetch
#pragma unroll
    for (int q = 0; q < 8; q++) {
        int id = tid + q * ATTN_THREADS;
        int n = id >> 3, kq = id & 7;
        cp_async16(base + HS_OFF0 + sw128((uint32_t)n * 128u + (uint32_t)kq * 16u),
                   g_HT + (size_t)n * NNODES + kq * 8);
    }
    cp_commit();

    // P(0): synchronous M load + compute into ps0
    {
#pragma unroll
        for (int j = 0; j < 4; j++) {
            const float4 m4 = *reinterpret_cast<const float4*>(Mrow + j * 4);
            const float4 t4 = *reinterpret_cast<const float4*>(Trow + j * 4);
            float pr[4];
#pragma unroll
            for (int e = 0; e < 4; e++) {
                float m = (&m4.x)[e];
                float v = si + (&t4.x)[e];
                float lr = fmaxf(v, NEG_SLOPE * v);
                float pv = (m > 0.f) ? __expf(m * lr) : 0.f;
                pr[e] = __bfloat162float(__float2bfloat16(pv));
            }
            __nv_bfloat162 p01 = __floats2bfloat162_rn(pr[0], pr[1]);
            __nv_bfloat162 p23 = __floats2bfloat162_rn(pr[2], pr[3]);
            uint2 packed;
            packed.x = *reinterpret_cast<uint32_t*>(&p01);
            packed.y = *reinterpret_cast<uint32_t*>(&p23);
            uint32_t byte = (uint32_t)pr_r * 128u + (uint32_t)(pr_seg * 16 + j * 4) * 2u;
            *reinterpret_cast<uint2*>(al + PS_OFF0 + sw128(byte)) = packed;
            rs_reg += pr[0] + pr[1] + pr[2] + pr[3];
        }
    }

    // M(1) prefetch into regs
    float4 mcur[4];
#pragma unroll
    for (int j = 0; j < 4; j++)
        mcur[j] = *reinterpret_cast<const float4*>(Mrow + BK + j * 4);

#pragma unroll 1
    for (int c = 0; c < NCHUNK; ++c) {
        const int buf = c & 1;
        const uint32_t ps_off = buf ? PS_OFF1 : PS_OFF0;
        const uint32_t hs_off = buf ? HS_OFF1 : HS_OFF0;

        cp_wait_all();
        __syncthreads();   // single barrier: Hs(c) visible, P(c) visible, prior-chunk readers done

        const int cn = c + 1;
        if (cn < NCHUNK) {
            const uint32_t hs_nxt = buf ? HS_OFF0 : HS_OFF1;
            const uint32_t ps_nxt = buf ? PS_OFF0 : PS_OFF1;
            // prefetch Hs(c+1)
#pragma unroll
            for (int q = 0; q < 8; q++) {
                int id = tid + q * ATTN_THREADS;
                int n = id >> 3, kq = id & 7;
                cp_async16(base + hs_nxt + sw128((uint32_t)n * 128u + (uint32_t)kq * 16u),
                           g_HT + (size_t)n * NNODES + cn * BK + kq * 8);
            }
            cp_commit();

            // prefetch M(c+2)
            float4 mnext[4];
            if (c + 2 < NCHUNK) {
#pragma unroll
                for (int j = 0; j < 4; j++)
                    mnext[j] = *reinterpret_cast<const float4*>(Mrow + (c + 2) * BK + j * 4);
            }

            // compute P(c+1) from mcur into ps_nxt
#pragma unroll
            for (int j = 0; j < 4; j++) {
                const float4 t4 = *reinterpret_cast<const float4*>(Trow + cn * BK + j * 4);
                float pr[4];
#pragma unroll
                for (int e = 0; e < 4; e++) {
                    float m = (&mcur[j].x)[e];
                    float v = si + (&t4.x)[e];
                    float lr = fmaxf(v, NEG_SLOPE * v);
                    float pv = (m > 0.f) ? __expf(m * lr) : 0.f;
                    pr[e] = __bfloat162float(__float2bfloat16(pv));
                }
                __nv_bfloat162 p01 = __floats2bfloat162_rn(pr[0], pr[1]);
                __nv_bfloat162 p23 = __floats2bfloat162_rn(pr[2], pr[3]);
                uint2 packed;
                packed.x = *reinterpret_cast<uint32_t*>(&p01);
                packed.y = *reinterpret_cast<uint32_t*>(&p23);
                uint32_t byte = (uint32_t)pr_r * 128u + (uint32_t)(pr_seg * 16 + j * 4) * 2u;
                *reinterpret_cast<uint2*>(al + ps_nxt + sw128(byte)) = packed;
                rs_reg += pr[0] + pr[1] + pr[2] + pr[3];
            }
#pragma unroll
            for (int j = 0; j < 4; j++) mcur[j] = mnext[j];
        }

        // MMA(c)
#pragma unroll
        for (int ks = 0; ks < 4; ks++) {
            const uint32_t kb = (uint32_t)(ks * 16 + (lane >> 4) * 8) * 2u;
            uint32_t a[2][4];
#pragma unroll
            for (int mt = 0; mt < 2; mt++) {
                uint32_t addr = base + ps_off +
                    sw128((uint32_t)(mrow0 + mt * 16 + (lane & 15)) * 128u + kb);
                ldm_x4(a[mt][0], a[mt][1], a[mt][2], a[mt][3], addr);
            }
            uint32_t b[8][2];
#pragma unroll
            for (int np = 0; np < 4; np++) {
                uint32_t r0, r1, r2, r3;
                uint32_t addr = base + hs_off +
                    sw128((uint32_t)(ncol0 + np * 16 + (lane & 15)) * 128u + kb);
                ldm_x4(r0, r1, r2, r3, addr);
                b[2 * np][0] = r0; b[2 * np][1] = r2;
                b[2 * np + 1][0] = r1; b[2 * np + 1][1] = r3;
            }
#pragma unroll
            for (int mt = 0; mt < 2; mt++)
#pragma unroll
                for (int nt = 0; nt < 8; nt++)
                    mma_16816(acc[mt][nt], a[mt], b[nt]);
        }
    }

    // rowsum reduce across the 4 threads of a row
    rs_reg += __shfl_xor_sync(0xffffffffu, rs_reg, 1);
    rs_reg += __shfl_xor_sync(0xffffffffu, rs_reg, 2);
    if ((tid & 3) == 0) rowsum[pr_r] = rs_reg;
    __syncthreads();

    // epilogue
#pragma unroll
    for (int mt = 0; mt < 2; mt++) {
#pragma unroll
        for (int half = 0; half < 2; half++) {
            const int rl = mrow0 + mt * 16 + (lane >> 2) + half * 8;
            const int row = row0 + rl;
            const float rs = rowsum[rl];
            const bool nb = !(rs > 0.f);
            const float inv = nb ? 0.f : 1.f / rs;
#pragma unroll
            for (int nt = 0; nt < 8; nt++) {
                const int col = ncol0 + nt * 8 + (lane & 3) * 2;
                float u0 = acc[mt][nt][2 * half]     * inv;
                float u1 = acc[mt][nt][2 * half + 1] * inv;
                if (nb) {
                    u0 = g_H[(size_t)row * FOUT + col];
                    u1 = g_H[(size_t)row * FOUT + col + 1];
                }
                float2 z;
                z.x = 1.f / (1.f + __expf(-u0));
                z.y = 1.f / (1.f + __expf(-u1));
                *reinterpret_cast<float2*>(out + (size_t)row * FOUT + col) = z;
            }
        }
    }
}

// ---------------- launch ----------------
extern "C" void kernel_launch(void* const* d_in, const int* in_sizes, int n_in,
                              void* d_out, int out_size) {
    const float *X = nullptr, *M = nullptr, *W = nullptr, *AW = nullptr;
    for (int i = 0; i < n_in; i++) {
        switch (in_sizes[i]) {
            case NNODES * FIN:    X  = (const float*)d_in[i]; break;
            case NNODES * NNODES: M  = (const float*)d_in[i]; break;
            case FOUT * FIN:      W  = (const float*)d_in[i]; break;
            case 2 * FOUT:        AW = (const float*)d_in[i]; break;
            default: break;
        }
    }
    float* out = (float*)d_out;

    cudaFuncSetAttribute(gemm_H_tf32_kernel,
                         cudaFuncAttributeMaxDynamicSharedMemorySize, GEMM_SMEM);
    cudaFuncSetAttribute(attn_mma_kernel,
                         cudaFuncAttributeMaxDynamicSharedMemorySize, SMEM_DYN);

    dim3 gH(NNODES / 128, FOUT / 64);
    gemm_H_tf32_kernel<<<gH, 256, GEMM_SMEM>>>(X, W);
    st_kernel<<<NNODES / 8, 256>>>(AW);
    attn_mma_kernel<<<NNODES / BM, ATTN_THREADS, SMEM_DYN>>>(M, out);
}

// round 5
// speedup vs baseline: 6.3451x; 1.2202x over previous
#include <cuda_runtime.h>
#include <cuda_bf16.h>
#include <math_constants.h>
#include <cstdint>

#define NNODES 8192
#define FIN    512
#define FOUT   256
#define NEG_SLOPE 0.2f

#define BM 64
#define BK 64
#define NCHUNK (NNODES / BK)     // 128
#define ATTN_THREADS 512

// ---------------- device scratch ----------------
__device__ float         g_H [NNODES * FOUT];   // H fp32 row-major
__device__ __nv_bfloat16 g_HT[FOUT * NNODES];   // H^T bf16 (n-major rows, k contiguous)
__device__ float         g_s [NNODES];
__device__ float         g_t [NNODES];

// ---------------- helpers (base PTX, sm_80-compatible) ----------------
static __device__ __forceinline__ uint32_t smem_u32(const void* p) {
    uint32_t a;
    asm("{ .reg .u64 t; cvta.to.shared.u64 t, %1; cvt.u32.u64 %0, t; }" : "=r"(a) : "l"(p));
    return a;
}
static __device__ __forceinline__ void cp_async16(uint32_t dst, const void* src) {
    asm volatile("cp.async.cg.shared.global [%0], [%1], 16;" :: "r"(dst), "l"(src));
}
static __device__ __forceinline__ void cp_commit() {
    asm volatile("cp.async.commit_group;" ::: "memory");
}
static __device__ __forceinline__ void cp_wait_all() {
    asm volatile("cp.async.wait_group 0;" ::: "memory");
}
static __device__ __forceinline__ void ldm_x4(uint32_t& r0, uint32_t& r1,
                                              uint32_t& r2, uint32_t& r3, uint32_t addr) {
    asm volatile("ldmatrix.sync.aligned.m8n8.x4.shared.b16 {%0, %1, %2, %3}, [%4];"
                 : "=r"(r0), "=r"(r1), "=r"(r2), "=r"(r3) : "r"(addr));
}
static __device__ __forceinline__ void mma_16816(float* d, const uint32_t* a, const uint32_t* b) {
    asm volatile(
        "mma.sync.aligned.m16n8k16.row.col.f32.bf16.bf16.f32 "
        "{%0, %1, %2, %3}, {%4, %5, %6, %7}, {%8, %9}, {%0, %1, %2, %3};"
        : "+f"(d[0]), "+f"(d[1]), "+f"(d[2]), "+f"(d[3])
        : "r"(a[0]), "r"(a[1]), "r"(a[2]), "r"(a[3]), "r"(b[0]), "r"(b[1]));
}
static __device__ __forceinline__ void mma_tf32(float* d, const uint32_t* a, const uint32_t* b) {
    asm volatile(
        "mma.sync.aligned.m16n8k8.row.col.f32.tf32.tf32.f32 "
        "{%0, %1, %2, %3}, {%4, %5, %6, %7}, {%8, %9}, {%0, %1, %2, %3};"
        : "+f"(d[0]), "+f"(d[1]), "+f"(d[2]), "+f"(d[3])
        : "r"(a[0]), "r"(a[1]), "r"(a[2]), "r"(a[3]), "r"(b[0]), "r"(b[1]));
}
static __device__ __forceinline__ uint32_t f2tf32(float v) {
    uint32_t r;
    asm("cvt.rna.tf32.f32 %0, %1;" : "=r"(r) : "f"(v));
    return r;
}
static __device__ __forceinline__ uint32_t sw128(uint32_t b) { return b ^ ((b >> 3) & 0x70); }

// ---------------- Kernel 1: H = X @ W^T via tf32 mma ----------------
#define GPITCH 36
#define XS_OFF0 0u
#define XS_OFF1 18432u
#define WS_OFF0 36864u
#define WS_OFF1 46080u
#define GEMM_SMEM 55296

__global__ void __launch_bounds__(256)
gemm_H_tf32_kernel(const float* __restrict__ X, const float* __restrict__ W) {
    extern __shared__ char gsm[];
    const uint32_t base = smem_u32(gsm);
    float* sm = (float*)gsm;

    const int tid = threadIdx.x;
    const int lane = tid & 31;
    const int wid = tid >> 5;
    const int wm = (wid & 3) * 32;
    const int wn = (wid >> 2) * 32;
    const int row0 = blockIdx.x * 128;
    const int col0 = blockIdx.y * 64;

    float acc[2][4][4];
#pragma unroll
    for (int mt = 0; mt < 2; mt++)
#pragma unroll
        for (int nt = 0; nt < 4; nt++)
#pragma unroll
            for (int e = 0; e < 4; e++) acc[mt][nt][e] = 0.f;

#pragma unroll
    for (int q = 0; q < 4; q++) {
        int id = tid + q * 256;
        int r = id >> 3, kq = id & 7;
        cp_async16(base + XS_OFF0 + (uint32_t)(r * GPITCH + kq * 4) * 4u,
                   X + (size_t)(row0 + r) * FIN + kq * 4);
    }
#pragma unroll
    for (int q = 0; q < 2; q++) {
        int id = tid + q * 256;
        int r = id >> 3, kq = id & 7;
        cp_async16(base + WS_OFF0 + (uint32_t)(r * GPITCH + kq * 4) * 4u,
                   W + (size_t)(col0 + r) * FIN + kq * 4);
    }
    cp_commit();

    const int a_r = lane >> 2;
    const int a_k = lane & 3;

#pragma unroll 1
    for (int kb = 0; kb < FIN / 32; kb++) {
        const int buf = kb & 1;
        const uint32_t xs = buf ? XS_OFF1 : XS_OFF0;
        const uint32_t ws = buf ? WS_OFF1 : WS_OFF0;
        cp_wait_all();
        __syncthreads();

        if (kb + 1 < FIN / 32) {
            const uint32_t xsn = buf ? XS_OFF0 : XS_OFF1;
            const uint32_t wsn = buf ? WS_OFF0 : WS_OFF1;
            const int k0n = (kb + 1) * 32;
#pragma unroll
            for (int q = 0; q < 4; q++) {
                int id = tid + q * 256;
                int r = id >> 3, kq = id & 7;
                cp_async16(base + xsn + (uint32_t)(r * GPITCH + kq * 4) * 4u,
                           X + (size_t)(row0 + r) * FIN + k0n + kq * 4);
            }
#pragma unroll
            for (int q = 0; q < 2; q++) {
                int id = tid + q * 256;
                int r = id >> 3, kq = id & 7;
                cp_async16(base + wsn + (uint32_t)(r * GPITCH + kq * 4) * 4u,
                           W + (size_t)(col0 + r) * FIN + k0n + kq * 4);
            }
            cp_commit();
        }

        const float* Xs = (const float*)((const char*)sm + xs);
        const float* Ws = (const float*)((const char*)sm + ws);
#pragma unroll
        for (int kk = 0; kk < 32; kk += 8) {
            uint32_t a[2][4];
#pragma unroll
            for (int mt = 0; mt < 2; mt++) {
                const int m = wm + mt * 16 + a_r;
                a[mt][0] = f2tf32(Xs[m * GPITCH + kk + a_k]);
                a[mt][1] = f2tf32(Xs[(m + 8) * GPITCH + kk + a_k]);
                a[mt][2] = f2tf32(Xs[m * GPITCH + kk + a_k + 4]);
                a[mt][3] = f2tf32(Xs[(m + 8) * GPITCH + kk + a_k + 4]);
            }
            uint32_t b[4][2];
#pragma unroll
            for (int nt = 0; nt < 4; nt++) {
                const int n = wn + nt * 8 + a_r;
                b[nt][0] = f2tf32(Ws[n * GPITCH + kk + a_k]);
                b[nt][1] = f2tf32(Ws[n * GPITCH + kk + a_k + 4]);
            }
#pragma unroll
            for (int mt = 0; mt < 2; mt++)
#pragma unroll
                for (int nt = 0; nt < 4; nt++)
                    mma_tf32(acc[mt][nt], a[mt], b[nt]);
        }
    }

#pragma unroll
    for (int mt = 0; mt < 2; mt++) {
#pragma unroll
        for (int nt = 0; nt < 4; nt++) {
#pragma unroll
            for (int half = 0; half < 2; half++) {
                const int row = row0 + wm + mt * 16 + (lane >> 2) + half * 8;
                const int col = col0 + wn + nt * 8 + (lane & 3) * 2;
                float v0 = acc[mt][nt][2 * half];
                float v1 = acc[mt][nt][2 * half + 1];
                *reinterpret_cast<float2*>(g_H + (size_t)row * FOUT + col) = make_float2(v0, v1);
                g_HT[(size_t)col * NNODES + row]       = __float2bfloat16(v0);
                g_HT[(size_t)(col + 1) * NNODES + row] = __float2bfloat16(v1);
            }
        }
    }
}

// ---------------- Kernel 2: s = H a_l, t = H a_r ----------------
__global__ void st_kernel(const float* __restrict__ attn_w) {
    const int lane = threadIdx.x & 31;
    const int warp = threadIdx.x >> 5;
    const int row = blockIdx.x * 8 + warp;
    float s = 0.f, t = 0.f;
#pragma unroll
    for (int o = lane; o < FOUT; o += 32) {
        float h = g_H[(size_t)row * FOUT + o];
        s += h * attn_w[o];
        t += h * attn_w[FOUT + o];
    }
#pragma unroll
    for (int off = 16; off; off >>= 1) {
        s += __shfl_down_sync(0xffffffffu, s, off);
        t += __shfl_down_sync(0xffffffffu, t, off);
    }
    if (lane == 0) { g_s[row] = s; g_t[row] = t; }
}

// ---------------- Kernel 3: pipelined flash attention, 512 threads ----------------
#define PS_OFF0 0u
#define PS_OFF1 8192u
#define HS_OFF0 16384u
#define HS_OFF1 49152u
#define RS_OFF  81920u
#define SMEM_DYN 83456

__global__ void __launch_bounds__(ATTN_THREADS)
attn_mma_kernel(const float* __restrict__ M, float* __restrict__ out) {
    extern __shared__ char dsm[];
    const uint32_t raw = smem_u32(dsm);
    const uint32_t base = (raw + 1023u) & ~1023u;
    char* al = dsm + (base - raw);

    const int tid  = threadIdx.x;
    const int lane = tid & 31;
    const int wid  = tid >> 5;
    const int row0 = blockIdx.x * BM;

    float* rowsum = (float*)(al + RS_OFF);

    // P-producer: row = tid/8, 8 cols at (tid%8)*8
    const int pr_r   = tid >> 3;
    const int pr_seg = tid & 7;
    const float si = g_s[row0 + pr_r];
    const float* Mrow = M + (size_t)(row0 + pr_r) * NNODES + pr_seg * 8;
    const float* Trow = g_t + pr_seg * 8;

    // warp MMA tile: 32 rows x 32 cols. 16 warps: 2 m-groups x 8 n-groups
    const int mrow0 = (wid & 1) * 32;
    const int ncol0 = (wid >> 1) * 32;

    float acc[2][4][4];
#pragma unroll
    for (int mt = 0; mt < 2; mt++)
#pragma unroll
        for (int nt = 0; nt < 4; nt++)
#pragma unroll
            for (int e = 0; e < 4; e++) acc[mt][nt][e] = 0.f;

    float rs_reg = 0.f;

    // ---- prologue: Hs(0) ----
#pragma unroll
    for (int q = 0; q < 4; q++) {
        int id = tid + q * ATTN_THREADS;
        int n = id >> 3, kq = id & 7;
        cp_async16(base + HS_OFF0 + sw128((uint32_t)n * 128u + (uint32_t)kq * 16u),
                   g_HT + (size_t)n * NNODES + kq * 8);
    }
    cp_commit();

    // P(0) synchronous
    {
#pragma unroll
        for (int j = 0; j < 2; j++) {
            const float4 m4 = *reinterpret_cast<const float4*>(Mrow + j * 4);
            const float4 t4 = *reinterpret_cast<const float4*>(Trow + j * 4);
            float pr[4];
#pragma unroll
            for (int e = 0; e < 4; e++) {
                float m = (&m4.x)[e];
                float v = si + (&t4.x)[e];
                float lr = fmaxf(v, NEG_SLOPE * v);
                float pv = (m > 0.f) ? __expf(m * lr) : 0.f;
                pr[e] = __bfloat162float(__float2bfloat16(pv));
            }
            __nv_bfloat162 p01 = __floats2bfloat162_rn(pr[0], pr[1]);
            __nv_bfloat162 p23 = __floats2bfloat162_rn(pr[2], pr[3]);
            uint2 packed;
            packed.x = *reinterpret_cast<uint32_t*>(&p01);
            packed.y = *reinterpret_cast<uint32_t*>(&p23);
            uint32_t byte = (uint32_t)pr_r * 128u + (uint32_t)(pr_seg * 8 + j * 4) * 2u;
            *reinterpret_cast<uint2*>(al + PS_OFF0 + sw128(byte)) = packed;
            rs_reg += pr[0] + pr[1] + pr[2] + pr[3];
        }
    }

    // M(1) prefetch
    float4 mcur[2];
#pragma unroll
    for (int j = 0; j < 2; j++)
        mcur[j] = *reinterpret_cast<const float4*>(Mrow + BK + j * 4);

#pragma unroll 1
    for (int c = 0; c < NCHUNK; ++c) {
        const int buf = c & 1;
        const uint32_t ps_off = buf ? PS_OFF1 : PS_OFF0;
        const uint32_t hs_off = buf ? HS_OFF1 : HS_OFF0;

        cp_wait_all();
        __syncthreads();

        const int cn = c + 1;
        if (cn < NCHUNK) {
            const uint32_t hs_nxt = buf ? HS_OFF0 : HS_OFF1;
            const uint32_t ps_nxt = buf ? PS_OFF0 : PS_OFF1;
#pragma unroll
            for (int q = 0; q < 4; q++) {
                int id = tid + q * ATTN_THREADS;
                int n = id >> 3, kq = id & 7;
                cp_async16(base + hs_nxt + sw128((uint32_t)n * 128u + (uint32_t)kq * 16u),
                           g_HT + (size_t)n * NNODES + cn * BK + kq * 8);
            }
            cp_commit();

            float4 mnext[2];
            if (c + 2 < NCHUNK) {
#pragma unroll
                for (int j = 0; j < 2; j++)
                    mnext[j] = *reinterpret_cast<const float4*>(Mrow + (c + 2) * BK + j * 4);
            }

            // P(c+1)
#pragma unroll
            for (int j = 0; j < 2; j++) {
                const float4 t4 = *reinterpret_cast<const float4*>(Trow + cn * BK + j * 4);
                float pr[4];
#pragma unroll
                for (int e = 0; e < 4; e++) {
                    float m = (&mcur[j].x)[e];
                    float v = si + (&t4.x)[e];
                    float lr = fmaxf(v, NEG_SLOPE * v);
                    float pv = (m > 0.f) ? __expf(m * lr) : 0.f;
                    pr[e] = __bfloat162float(__float2bfloat16(pv));
                }
                __nv_bfloat162 p01 = __floats2bfloat162_rn(pr[0], pr[1]);
                __nv_bfloat162 p23 = __floats2bfloat162_rn(pr[2], pr[3]);
                uint2 packed;
                packed.x = *reinterpret_cast<uint32_t*>(&p01);
                packed.y = *reinterpret_cast<uint32_t*>(&p23);
                uint32_t byte = (uint32_t)pr_r * 128u + (uint32_t)(pr_seg * 8 + j * 4) * 2u;
                *reinterpret_cast<uint2*>(al + ps_nxt + sw128(byte)) = packed;
                rs_reg += pr[0] + pr[1] + pr[2] + pr[3];
            }
#pragma unroll
            for (int j = 0; j < 2; j++) mcur[j] = mnext[j];
        }

        // MMA(c): per warp 32x32 tile
#pragma unroll
        for (int ks = 0; ks < 4; ks++) {
            const uint32_t kb = (uint32_t)(ks * 16 + (lane >> 4) * 8) * 2u;
            uint32_t a[2][4];
#pragma unroll
            for (int mt = 0; mt < 2; mt++) {
                uint32_t addr = base + ps_off +
                    sw128((uint32_t)(mrow0 + mt * 16 + (lane & 15)) * 128u + kb);
                ldm_x4(a[mt][0], a[mt][1], a[mt][2], a[mt][3], addr);
            }
            uint32_t b[4][2];
#pragma unroll
            for (int np = 0; np < 2; np++) {
                uint32_t r0, r1, r2, r3;
                uint32_t addr = base + hs_off +
                    sw128((uint32_t)(ncol0 + np * 16 + (lane & 15)) * 128u + kb);
                ldm_x4(r0, r1, r2, r3, addr);
                b[2 * np][0] = r0; b[2 * np][1] = r2;
                b[2 * np + 1][0] = r1; b[2 * np + 1][1] = r3;
            }
#pragma unroll
            for (int mt = 0; mt < 2; mt++)
#pragma unroll
                for (int nt = 0; nt < 4; nt++)
                    mma_16816(acc[mt][nt], a[mt], b[nt]);
        }
    }

    // rowsum: reduce across the 8 threads of a row (lanes within warp)
    rs_reg += __shfl_xor_sync(0xffffffffu, rs_reg, 1);
    rs_reg += __shfl_xor_sync(0xffffffffu, rs_reg, 2);
    rs_reg += __shfl_xor_sync(0xffffffffu, rs_reg, 4);
    if ((tid & 7) == 0) rowsum[pr_r] = rs_reg;
    __syncthreads();

    // epilogue
#pragma unroll
    for (int mt = 0; mt < 2; mt++) {
#pragma unroll
        for (int half = 0; half < 2; half++) {
            const int rl = mrow0 + mt * 16 + (lane >> 2) + half * 8;
            const int row = row0 + rl;
            const float rs = rowsum[rl];
            const bool nb = !(rs > 0.f);
            const float inv = nb ? 0.f : 1.f / rs;
#pragma unroll
            for (int nt = 0; nt < 4; nt++) {
                const int col = ncol0 + nt * 8 + (lane & 3) * 2;
                float u0 = acc[mt][nt][2 * half]     * inv;
                float u1 = acc[mt][nt][2 * half + 1] * inv;
                if (nb) {
                    u0 = g_H[(size_t)row * FOUT + col];
                    u1 = g_H[(size_t)row * FOUT + col + 1];
                }
                float2 z;
                z.x = 1.f / (1.f + __expf(-u0));
                z.y = 1.f / (1.f + __expf(-u1));
                *reinterpret_cast<float2*>(out + (size_t)row * FOUT + col) = z;
            }
        }
    }
}

// ---------------- launch ----------------
extern "C" void kernel_launch(void* const* d_in, const int* in_sizes, int n_in,
                              void* d_out, int out_size) {
    const float *X = nullptr, *M = nullptr, *W = nullptr, *AW = nullptr;
    for (int i = 0; i < n_in; i++) {
        switch (in_sizes[i]) {
            case NNODES * FIN:    X  = (const float*)d_in[i]; break;
            case NNODES * NNODES: M  = (const float*)d_in[i]; break;
            case FOUT * FIN:      W  = (const float*)d_in[i]; break;
            case 2 * FOUT:        AW = (const float*)d_in[i]; break;
            default: break;
        }
    }
    float* out = (float*)d_out;

    cudaFuncSetAttribute(gemm_H_tf32_kernel,
                         cudaFuncAttributeMaxDynamicSharedMemorySize, GEMM_SMEM);
    cudaFuncSetAttribute(attn_mma_kernel,
                         cudaFuncAttributeMaxDynamicSharedMemorySize, SMEM_DYN);

    dim3 gH(NNODES / 128, FOUT / 64);
    gemm_H_tf32_kernel<<<gH, 256, GEMM_SMEM>>>(X, W);
    st_kernel<<<NNODES / 8, 256>>>(AW);
    attn_mma_kernel<<<NNODES / BM, ATTN_THREADS, SMEM_DYN>>>(M, out);
}

// round 6
// speedup vs baseline: 7.1710x; 1.1302x over previous
#include <cuda_runtime.h>
#include <cuda_bf16.h>
#include <math_constants.h>
#include <cstdint>

#define NNODES 8192
#define FIN    512
#define FOUT   256
#define NEG_SLOPE 0.2f

#define BM 64
#define BK 64
#define NCHUNK (NNODES / BK)     // 128
#define ATTN_THREADS 1024

// ---------------- device scratch ----------------
__device__ float         g_H [NNODES * FOUT];   // H fp32 row-major
__device__ __nv_bfloat16 g_HT[FOUT * NNODES];   // H^T bf16 (n-major rows, k contiguous)
__device__ float         g_s [NNODES];
__device__ float         g_t [NNODES];

// ---------------- helpers (base PTX, sm_80-compatible) ----------------
static __device__ __forceinline__ uint32_t smem_u32(const void* p) {
    uint32_t a;
    asm("{ .reg .u64 t; cvta.to.shared.u64 t, %1; cvt.u32.u64 %0, t; }" : "=r"(a) : "l"(p));
    return a;
}
static __device__ __forceinline__ void cp_async16(uint32_t dst, const void* src) {
    asm volatile("cp.async.cg.shared.global [%0], [%1], 16;" :: "r"(dst), "l"(src));
}
static __device__ __forceinline__ void cp_commit() {
    asm volatile("cp.async.commit_group;" ::: "memory");
}
static __device__ __forceinline__ void cp_wait_all() {
    asm volatile("cp.async.wait_group 0;" ::: "memory");
}
static __device__ __forceinline__ void ldm_x4(uint32_t& r0, uint32_t& r1,
                                              uint32_t& r2, uint32_t& r3, uint32_t addr) {
    asm volatile("ldmatrix.sync.aligned.m8n8.x4.shared.b16 {%0, %1, %2, %3}, [%4];"
                 : "=r"(r0), "=r"(r1), "=r"(r2), "=r"(r3) : "r"(addr));
}
static __device__ __forceinline__ void mma_16816(float* d, const uint32_t* a, const uint32_t* b) {
    asm volatile(
        "mma.sync.aligned.m16n8k16.row.col.f32.bf16.bf16.f32 "
        "{%0, %1, %2, %3}, {%4, %5, %6, %7}, {%8, %9}, {%0, %1, %2, %3};"
        : "+f"(d[0]), "+f"(d[1]), "+f"(d[2]), "+f"(d[3])
        : "r"(a[0]), "r"(a[1]), "r"(a[2]), "r"(a[3]), "r"(b[0]), "r"(b[1]));
}
static __device__ __forceinline__ void mma_tf32(float* d, const uint32_t* a, const uint32_t* b) {
    asm volatile(
        "mma.sync.aligned.m16n8k8.row.col.f32.tf32.tf32.f32 "
        "{%0, %1, %2, %3}, {%4, %5, %6, %7}, {%8, %9}, {%0, %1, %2, %3};"
        : "+f"(d[0]), "+f"(d[1]), "+f"(d[2]), "+f"(d[3])
        : "r"(a[0]), "r"(a[1]), "r"(a[2]), "r"(a[3]), "r"(b[0]), "r"(b[1]));
}
static __device__ __forceinline__ uint32_t f2tf32(float v) {
    uint32_t r;
    asm("cvt.rna.tf32.f32 %0, %1;" : "=r"(r) : "f"(v));
    return r;
}
static __device__ __forceinline__ uint32_t sw128(uint32_t b) { return b ^ ((b >> 3) & 0x70); }

// ---------------- Kernel 1: H = X @ W^T via tf32 mma ----------------
#define GPITCH 36
#define XS_OFF0 0u
#define XS_OFF1 18432u
#define WS_OFF0 36864u
#define WS_OFF1 46080u
#define GEMM_SMEM 55296

__global__ void __launch_bounds__(256)
gemm_H_tf32_kernel(const float* __restrict__ X, const float* __restrict__ W) {
    extern __shared__ char gsm[];
    const uint32_t base = smem_u32(gsm);
    float* sm = (float*)gsm;

    const int tid = threadIdx.x;
    const int lane = tid & 31;
    const int wid = tid >> 5;
    const int wm = (wid & 3) * 32;
    const int wn = (wid >> 2) * 32;
    const int row0 = blockIdx.x * 128;
    const int col0 = blockIdx.y * 64;

    float acc[2][4][4];
#pragma unroll
    for (int mt = 0; mt < 2; mt++)
#pragma unroll
        for (int nt = 0; nt < 4; nt++)
#pragma unroll
            for (int e = 0; e < 4; e++) acc[mt][nt][e] = 0.f;

#pragma unroll
    for (int q = 0; q < 4; q++) {
        int id = tid + q * 256;
        int r = id >> 3, kq = id & 7;
        cp_async16(base + XS_OFF0 + (uint32_t)(r * GPITCH + kq * 4) * 4u,
                   X + (size_t)(row0 + r) * FIN + kq * 4);
    }
#pragma unroll
    for (int q = 0; q < 2; q++) {
        int id = tid + q * 256;
        int r = id >> 3, kq = id & 7;
        cp_async16(base + WS_OFF0 + (uint32_t)(r * GPITCH + kq * 4) * 4u,
                   W + (size_t)(col0 + r) * FIN + kq * 4);
    }
    cp_commit();

    const int a_r = lane >> 2;
    const int a_k = lane & 3;

#pragma unroll 1
    for (int kb = 0; kb < FIN / 32; kb++) {
        const int buf = kb & 1;
        const uint32_t xs = buf ? XS_OFF1 : XS_OFF0;
        const uint32_t ws = buf ? WS_OFF1 : WS_OFF0;
        cp_wait_all();
        __syncthreads();

        if (kb + 1 < FIN / 32) {
            const uint32_t xsn = buf ? XS_OFF0 : XS_OFF1;
            const uint32_t wsn = buf ? WS_OFF0 : WS_OFF1;
            const int k0n = (kb + 1) * 32;
#pragma unroll
            for (int q = 0; q < 4; q++) {
                int id = tid + q * 256;
                int r = id >> 3, kq = id & 7;
                cp_async16(base + xsn + (uint32_t)(r * GPITCH + kq * 4) * 4u,
                           X + (size_t)(row0 + r) * FIN + k0n + kq * 4);
            }
#pragma unroll
            for (int q = 0; q < 2; q++) {
                int id = tid + q * 256;
                int r = id >> 3, kq = id & 7;
                cp_async16(base + wsn + (uint32_t)(r * GPITCH + kq * 4) * 4u,
                           W + (size_t)(col0 + r) * FIN + k0n + kq * 4);
            }
            cp_commit();
        }

        const float* Xs = (const float*)((const char*)sm + xs);
        const float* Ws = (const float*)((const char*)sm + ws);
#pragma unroll
        for (int kk = 0; kk < 32; kk += 8) {
            uint32_t a[2][4];
#pragma unroll
            for (int mt = 0; mt < 2; mt++) {
                const int m = wm + mt * 16 + a_r;
                a[mt][0] = f2tf32(Xs[m * GPITCH + kk + a_k]);
                a[mt][1] = f2tf32(Xs[(m + 8) * GPITCH + kk + a_k]);
                a[mt][2] = f2tf32(Xs[m * GPITCH + kk + a_k + 4]);
                a[mt][3] = f2tf32(Xs[(m + 8) * GPITCH + kk + a_k + 4]);
            }
            uint32_t b[4][2];
#pragma unroll
            for (int nt = 0; nt < 4; nt++) {
                const int n = wn + nt * 8 + a_r;
                b[nt][0] = f2tf32(Ws[n * GPITCH + kk + a_k]);
                b[nt][1] = f2tf32(Ws[n * GPITCH + kk + a_k + 4]);
            }
#pragma unroll
            for (int mt = 0; mt < 2; mt++)
#pragma unroll
                for (int nt = 0; nt < 4; nt++)
                    mma_tf32(acc[mt][nt], a[mt], b[nt]);
        }
    }

#pragma unroll
    for (int mt = 0; mt < 2; mt++) {
#pragma unroll
        for (int nt = 0; nt < 4; nt++) {
#pragma unroll
            for (int half = 0; half < 2; half++) {
                const int row = row0 + wm + mt * 16 + (lane >> 2) + half * 8;
                const int col = col0 + wn + nt * 8 + (lane & 3) * 2;
                float v0 = acc[mt][nt][2 * half];
                float v1 = acc[mt][nt][2 * half + 1];
                *reinterpret_cast<float2*>(g_H + (size_t)row * FOUT + col) = make_float2(v0, v1);
                g_HT[(size_t)col * NNODES + row]       = __float2bfloat16(v0);
                g_HT[(size_t)(col + 1) * NNODES + row] = __float2bfloat16(v1);
            }
        }
    }
}

// ---------------- Kernel 2: s = H a_l, t = H a_r ----------------
__global__ void st_kernel(const float* __restrict__ attn_w) {
    const int lane = threadIdx.x & 31;
    const int warp = threadIdx.x >> 5;
    const int row = blockIdx.x * 8 + warp;
    float s = 0.f, t = 0.f;
#pragma unroll
    for (int o = lane; o < FOUT; o += 32) {
        float h = g_H[(size_t)row * FOUT + o];
        s += h * attn_w[o];
        t += h * attn_w[FOUT + o];
    }
#pragma unroll
    for (int off = 16; off; off >>= 1) {
        s += __shfl_down_sync(0xffffffffu, s, off);
        t += __shfl_down_sync(0xffffffffu, t, off);
    }
    if (lane == 0) { g_s[row] = s; g_t[row] = t; }
}

// ---------------- Kernel 3: pipelined flash attention, 1024 threads / 32 warps ----------------
#define PS_OFF0 0u
#define PS_OFF1 8192u
#define HS_OFF0 16384u
#define HS_OFF1 49152u
#define RS_OFF  81920u
#define SMEM_DYN 83456

__global__ void __launch_bounds__(ATTN_THREADS, 1)
attn_mma_kernel(const float* __restrict__ M, float* __restrict__ out) {
    extern __shared__ char dsm[];
    const uint32_t raw = smem_u32(dsm);
    const uint32_t base = (raw + 1023u) & ~1023u;
    char* al = dsm + (base - raw);

    const int tid  = threadIdx.x;
    const int lane = tid & 31;
    const int wid  = tid >> 5;
    const int row0 = blockIdx.x * BM;

    float* rowsum = (float*)(al + RS_OFF);

    // P-producer: row = tid/16, 4 cols at (tid%16)*4
    const int pr_r   = tid >> 4;
    const int pr_seg = tid & 15;
    const float si = g_s[row0 + pr_r];
    const float* Mrow = M + (size_t)(row0 + pr_r) * NNODES + pr_seg * 4;
    const float* Trow = g_t + pr_seg * 4;

    // warp MMA tile: 16 rows x 32 cols. 32 warps: 4 m-groups x 8 n-groups
    const int mrow0 = (wid & 3) * 16;
    const int ncol0 = (wid >> 2) * 32;

    float acc[4][4];
#pragma unroll
    for (int nt = 0; nt < 4; nt++)
#pragma unroll
        for (int e = 0; e < 4; e++) acc[nt][e] = 0.f;

    float rs_reg = 0.f;

    // ---- prologue: Hs(0) ----
#pragma unroll
    for (int q = 0; q < 2; q++) {
        int id = tid + q * ATTN_THREADS;
        int n = id >> 3, kq = id & 7;
        cp_async16(base + HS_OFF0 + sw128((uint32_t)n * 128u + (uint32_t)kq * 16u),
                   g_HT + (size_t)n * NNODES + kq * 8);
    }
    cp_commit();

    // P(0) synchronous
    {
        const float4 m4 = *reinterpret_cast<const float4*>(Mrow);
        const float4 t4 = *reinterpret_cast<const float4*>(Trow);
        float pr[4];
#pragma unroll
        for (int e = 0; e < 4; e++) {
            float m = (&m4.x)[e];
            float v = si + (&t4.x)[e];
            float lr = fmaxf(v, NEG_SLOPE * v);
            float pv = (m > 0.f) ? __expf(m * lr) : 0.f;
            pr[e] = __bfloat162float(__float2bfloat16(pv));
        }
        __nv_bfloat162 p01 = __floats2bfloat162_rn(pr[0], pr[1]);
        __nv_bfloat162 p23 = __floats2bfloat162_rn(pr[2], pr[3]);
        uint2 packed;
        packed.x = *reinterpret_cast<uint32_t*>(&p01);
        packed.y = *reinterpret_cast<uint32_t*>(&p23);
        uint32_t byte = (uint32_t)pr_r * 128u + (uint32_t)(pr_seg * 4) * 2u;
        *reinterpret_cast<uint2*>(al + PS_OFF0 + sw128(byte)) = packed;
        rs_reg += pr[0] + pr[1] + pr[2] + pr[3];
    }

    // M(1) prefetch
    float4 mcur = *reinterpret_cast<const float4*>(Mrow + BK);

#pragma unroll 1
    for (int c = 0; c < NCHUNK; ++c) {
        const int buf = c & 1;
        const uint32_t ps_off = buf ? PS_OFF1 : PS_OFF0;
        const uint32_t hs_off = buf ? HS_OFF1 : HS_OFF0;

        cp_wait_all();
        __syncthreads();

        const int cn = c + 1;
        if (cn < NCHUNK) {
            const uint32_t hs_nxt = buf ? HS_OFF0 : HS_OFF1;
            const uint32_t ps_nxt = buf ? PS_OFF0 : PS_OFF1;
#pragma unroll
            for (int q = 0; q < 2; q++) {
                int id = tid + q * ATTN_THREADS;
                int n = id >> 3, kq = id & 7;
                cp_async16(base + hs_nxt + sw128((uint32_t)n * 128u + (uint32_t)kq * 16u),
                           g_HT + (size_t)n * NNODES + cn * BK + kq * 8);
            }
            cp_commit();

            float4 mnext;
            if (c + 2 < NCHUNK)
                mnext = *reinterpret_cast<const float4*>(Mrow + (c + 2) * BK);

            // P(c+1)
            {
                const float4 t4 = *reinterpret_cast<const float4*>(Trow + cn * BK);
                float pr[4];
#pragma unroll
                for (int e = 0; e < 4; e++) {
                    float m = (&mcur.x)[e];
                    float v = si + (&t4.x)[e];
                    float lr = fmaxf(v, NEG_SLOPE * v);
                    float pv = (m > 0.f) ? __expf(m * lr) : 0.f;
                    pr[e] = __bfloat162float(__float2bfloat16(pv));
                }
                __nv_bfloat162 p01 = __floats2bfloat162_rn(pr[0], pr[1]);
                __nv_bfloat162 p23 = __floats2bfloat162_rn(pr[2], pr[3]);
                uint2 packed;
                packed.x = *reinterpret_cast<uint32_t*>(&p01);
                packed.y = *reinterpret_cast<uint32_t*>(&p23);
                uint32_t byte = (uint32_t)pr_r * 128u + (uint32_t)(pr_seg * 4) * 2u;
                *reinterpret_cast<uint2*>(al + ps_nxt + sw128(byte)) = packed;
                rs_reg += pr[0] + pr[1] + pr[2] + pr[3];
            }
            mcur = mnext;
        }

        // MMA(c): per warp 16x32 tile
#pragma unroll
        for (int ks = 0; ks < 4; ks++) {
            const uint32_t kb = (uint32_t)(ks * 16 + (lane >> 4) * 8) * 2u;
            uint32_t a[4];
            {
                uint32_t addr = base + ps_off +
                    sw128((uint32_t)(mrow0 + (lane & 15)) * 128u + kb);
                ldm_x4(a[0], a[1], a[2], a[3], addr);
            }
            uint32_t b[4][2];
#pragma unroll
            for (int np = 0; np < 2; np++) {
                uint32_t r0, r1, r2, r3;
                uint32_t addr = base + hs_off +
                    sw128((uint32_t)(ncol0 + np * 16 + (lane & 15)) * 128u + kb);
                ldm_x4(r0, r1, r2, r3, addr);
                b[2 * np][0] = r0; b[2 * np][1] = r2;
                b[2 * np + 1][0] = r1; b[2 * np + 1][1] = r3;
            }
#pragma unroll
            for (int nt = 0; nt < 4; nt++)
                mma_16816(acc[nt], a, b[nt]);
        }
    }

    // rowsum: reduce across the 16 threads of a row (within 16-lane group)
    rs_reg += __shfl_xor_sync(0xffffffffu, rs_reg, 1);
    rs_reg += __shfl_xor_sync(0xffffffffu, rs_reg, 2);
    rs_reg += __shfl_xor_sync(0xffffffffu, rs_reg, 4);
    rs_reg += __shfl_xor_sync(0xffffffffu, rs_reg, 8);
    if ((tid & 15) == 0) rowsum[pr_r] = rs_reg;
    __syncthreads();

    // epilogue: warp tile 16x32
#pragma unroll
    for (int half = 0; half < 2; half++) {
        const int rl = mrow0 + (lane >> 2) + half * 8;
        const int row = row0 + rl;
        const float rs = rowsum[rl];
        const bool nb = !(rs > 0.f);
        const float inv = nb ? 0.f : 1.f / rs;
#pragma unroll
        for (int nt = 0; nt < 4; nt++) {
            const int col = ncol0 + nt * 8 + (lane & 3) * 2;
            float u0 = acc[nt][2 * half]     * inv;
            float u1 = acc[nt][2 * half + 1] * inv;
            if (nb) {
                u0 = g_H[(size_t)row * FOUT + col];
                u1 = g_H[(size_t)row * FOUT + col + 1];
            }
            float2 z;
            z.x = 1.f / (1.f + __expf(-u0));
            z.y = 1.f / (1.f + __expf(-u1));
            *reinterpret_cast<float2*>(out + (size_t)row * FOUT + col) = z;
        }
    }
}

// ---------------- launch ----------------
extern "C" void kernel_launch(void* const* d_in, const int* in_sizes, int n_in,
                              void* d_out, int out_size) {
    const float *X = nullptr, *M = nullptr, *W = nullptr, *AW = nullptr;
    for (int i = 0; i < n_in; i++) {
        switch (in_sizes[i]) {
            case NNODES * FIN:    X  = (const float*)d_in[i]; break;
            case NNODES * NNODES: M  = (const float*)d_in[i]; break;
            case FOUT * FIN:      W  = (const float*)d_in[i]; break;
            case 2 * FOUT:        AW = (const float*)d_in[i]; break;
            default: break;
        }
    }
    float* out = (float*)d_out;

    cudaFuncSetAttribute(gemm_H_tf32_kernel,
                         cudaFuncAttributeMaxDynamicSharedMemorySize, GEMM_SMEM);
    cudaFuncSetAttribute(attn_mma_kernel,
                         cudaFuncAttributeMaxDynamicSharedMemorySize, SMEM_DYN);

    dim3 gH(NNODES / 128, FOUT / 64);
    gemm_H_tf32_kernel<<<gH, 256, GEMM_SMEM>>>(X, W);
    st_kernel<<<NNODES / 8, 256>>>(AW);
    attn_mma_kernel<<<NNODES / BM, ATTN_THREADS, SMEM_DYN>>>(M, out);
}